// round 8
// baseline (speedup 1.0000x reference)
#include <cuda_runtime.h>

#define B_  16
#define NK_ 256
#define NQ_ 256
#define DK_ 256
#define H_  128
#define DV_ 256
#define KT  4     // k-rows per attn tile
#define RT  8     // rows per proj block
#define NTILES (B_ * NK_ / KT)   // 1024
#define PERSIST_BLOCKS 888       // 6 blocks/SM * 148 SMs

// scratch for projections (allocation-free rule: device globals)
__device__ float g_kproj[B_ * NK_ * H_];   // (B, NK, H)
__device__ float g_qproj[B_ * NQ_ * H_];   // (B, NQ, H)
__device__ int   g_tile_ctr;               // persistent work queue

__device__ __forceinline__ float tanh_fast(float x) {
    float y;
    asm("tanh.approx.f32 %0, %1;" : "=f"(y) : "f"(x));
    return y;
}

// ---------------------------------------------------------------------------
// Kernel A: projections, RT=8 rows per 128-thread block (R3/R7 config).
// Also resets the attn work-queue counter (stream-ordered before attn).
// ---------------------------------------------------------------------------
__global__ __launch_bounds__(128)
void proj_kernel(const float* __restrict__ key,
                 const float* __restrict__ query,
                 const float* __restrict__ Wk,
                 const float* __restrict__ Wq) {
    if (blockIdx.x == 0 && blockIdx.y == 0 && threadIdx.x == 0)
        g_tile_ctr = 0;

    __shared__ __align__(16) float rowsT[DK_ * RT];      // rowsT[d*RT + r]
    const float* in = blockIdx.y ? query : key;
    const float* W  = blockIdx.y ? Wq    : Wk;
    float* out      = blockIdx.y ? g_qproj : g_kproj;

    const int r0 = blockIdx.x * RT;
    const int t  = threadIdx.x;            // 0..127

    {
        const float* src = in + (size_t)r0 * DK_;
        int r = t >> 4;
        int d0 = (t & 15) * 16;
        #pragma unroll
        for (int i = 0; i < 4; ++i) {
            float4 v = *reinterpret_cast<const float4*>(src + r * DK_ + d0 + i * 4);
            rowsT[(d0 + i * 4 + 0) * RT + r] = v.x;
            rowsT[(d0 + i * 4 + 1) * RT + r] = v.y;
            rowsT[(d0 + i * 4 + 2) * RT + r] = v.z;
            rowsT[(d0 + i * 4 + 3) * RT + r] = v.w;
        }
    }
    __syncthreads();

    float acc[RT];
    #pragma unroll
    for (int r = 0; r < RT; ++r) acc[r] = 0.f;

    #pragma unroll 4
    for (int d = 0; d < DK_; ++d) {
        float w = W[d * H_ + t];
        float4 ra = *reinterpret_cast<const float4*>(&rowsT[d * RT]);
        float4 rb = *reinterpret_cast<const float4*>(&rowsT[d * RT + 4]);
        acc[0] = fmaf(ra.x, w, acc[0]);
        acc[1] = fmaf(ra.y, w, acc[1]);
        acc[2] = fmaf(ra.z, w, acc[2]);
        acc[3] = fmaf(ra.w, w, acc[3]);
        acc[4] = fmaf(rb.x, w, acc[4]);
        acc[5] = fmaf(rb.y, w, acc[5]);
        acc[6] = fmaf(rb.z, w, acc[6]);
        acc[7] = fmaf(rb.w, w, acc[7]);
    }

    #pragma unroll
    for (int r = 0; r < RT; ++r)
        out[(size_t)(r0 + r) * H_ + t] = acc[r];
}

// ---------------------------------------------------------------------------
// Kernel B: PERSISTENT. Each block loops over tiles from an atomic queue.
// Tile decode identical to R7 static mapping: b = tile>>6, k0 = (tile&63)*KT.
// Per-tile body identical to R7 (no-max softmax, valid_lens early-skip).
// ---------------------------------------------------------------------------
__global__ __launch_bounds__(256)
void attn_kernel(const float* __restrict__ value,
                 const int*   __restrict__ valid_lens,
                 const float* __restrict__ wv,
                 float*       __restrict__ out) {
    const int t   = threadIdx.x;         // 0..255
    const int lane = t & 31;
    const int wid  = t >> 5;

    __shared__ __align__(16) float kvs[KT * H_];       // 2KB
    __shared__ __align__(16) float wvs[H_];
    __shared__ __align__(16) float attnT[NQ_ * KT];    // 4KB, attnT[q*KT + k]
    __shared__ float redm[KT][8];
    __shared__ float gred[KT];
    __shared__ int   s_tile;

    if (t < H_) wvs[t] = wv[t];          // batch-invariant, load once

    for (;;) {
        __syncthreads();                 // prev tile fully consumed; s_tile free
        if (t == 0) s_tile = atomicAdd(&g_tile_ctr, 1);
        __syncthreads();
        const int tile = s_tile;
        if (tile >= NTILES) break;

        const int bk0 = tile * KT;
        const int b   = bk0 >> 8;        // NK = 256
        const int vl  = valid_lens[b];

        // stage KT kproj rows
        {
            const float* src = g_kproj + (size_t)bk0 * H_;   // 512 floats
            *reinterpret_cast<float2*>(&kvs[t * 2]) =
                *reinterpret_cast<const float2*>(src + t * 2);
        }
        __syncthreads();

        // ---- Phase 1: scores + exp for q = t, all KT k ----
        float e[KT];
        if (t < vl) {
            const float* qrow = g_qproj + (size_t)(b * NQ_ + t) * H_;
            float s[KT];
            #pragma unroll
            for (int k = 0; k < KT; ++k) s[k] = 0.f;

            #pragma unroll 2
            for (int h = 0; h < H_; h += 4) {
                float4 qv  = *reinterpret_cast<const float4*>(qrow + h);
                float4 wv4 = *reinterpret_cast<const float4*>(&wvs[h]);
                #pragma unroll
                for (int k = 0; k < KT; ++k) {
                    float4 kv = *reinterpret_cast<const float4*>(&kvs[k * H_ + h]);
                    s[k] = fmaf(wv4.x, tanh_fast(kv.x + qv.x), s[k]);
                    s[k] = fmaf(wv4.y, tanh_fast(kv.y + qv.y), s[k]);
                    s[k] = fmaf(wv4.z, tanh_fast(kv.z + qv.z), s[k]);
                    s[k] = fmaf(wv4.w, tanh_fast(kv.w + qv.w), s[k]);
                }
            }
            #pragma unroll
            for (int k = 0; k < KT; ++k)
                e[k] = __expf(s[k]);      // |s| <= ~9, safe without max-sub
        } else {
            #pragma unroll
            for (int k = 0; k < KT; ++k) e[k] = 0.f;
        }

        // ---- Phase 2: sum reduction per k over 256 q ----
        #pragma unroll
        for (int k = 0; k < KT; ++k) {
            float sm = e[k];
            #pragma unroll
            for (int o = 16; o > 0; o >>= 1)
                sm += __shfl_xor_sync(0xffffffffu, sm, o);
            if (lane == 0) redm[k][wid] = sm;
        }
        __syncthreads();
        if (t < 32) {                    // one warp: k = t>>3 (0..3)
            int k = t >> 3, w = t & 7;
            float v = redm[k][w];
            v += __shfl_xor_sync(0xffffffffu, v, 4);
            v += __shfl_xor_sync(0xffffffffu, v, 2);
            v += __shfl_xor_sync(0xffffffffu, v, 1);
            if (w == 0) gred[k] = v;
        }
        __syncthreads();

        {
            float4 a;
            a.x = e[0] * __frcp_rn(gred[0]);
            a.y = e[1] * __frcp_rn(gred[1]);
            a.z = e[2] * __frcp_rn(gred[2]);
            a.w = e[3] * __frcp_rn(gred[3]);
            *reinterpret_cast<float4*>(&attnT[t * KT]) = a;
        }
        __syncthreads();

        // ---- Phase 3: out[b, bk0+k, d], d = t; only q < vl contribute ----
        const float* vcol = value + (size_t)b * NQ_ * DV_ + t;
        float a0 = 0.f, a1 = 0.f, a2 = 0.f, a3 = 0.f;

        int q = 0;
        const int vl4 = vl & ~3;
        for (; q < vl4; q += 4) {
            #pragma unroll
            for (int j = 0; j < 4; ++j) {
                float v = vcol[(size_t)(q + j) * DV_];
                float4 a = *reinterpret_cast<const float4*>(&attnT[(q + j) * KT]);
                a0 = fmaf(a.x, v, a0);
                a1 = fmaf(a.y, v, a1);
                a2 = fmaf(a.z, v, a2);
                a3 = fmaf(a.w, v, a3);
            }
        }
        for (; q < vl; ++q) {
            float v = vcol[(size_t)q * DV_];
            float4 a = *reinterpret_cast<const float4*>(&attnT[q * KT]);
            a0 = fmaf(a.x, v, a0);
            a1 = fmaf(a.y, v, a1);
            a2 = fmaf(a.z, v, a2);
            a3 = fmaf(a.w, v, a3);
        }

        out[(size_t)(bk0 + 0) * DV_ + t] = a0;
        out[(size_t)(bk0 + 1) * DV_ + t] = a1;
        out[(size_t)(bk0 + 2) * DV_ + t] = a2;
        out[(size_t)(bk0 + 3) * DV_ + t] = a3;
    }
}

// ---------------------------------------------------------------------------
extern "C" void kernel_launch(void* const* d_in, const int* in_sizes, int n_in,
                              void* d_out, int out_size) {
    const float* key        = (const float*)d_in[0];
    const float* query      = (const float*)d_in[1];
    const float* value      = (const float*)d_in[2];
    const int*   valid_lens = (const int*)  d_in[3];
    const float* Wk         = (const float*)d_in[4];
    const float* Wq         = (const float*)d_in[5];
    const float* wv         = (const float*)d_in[6];
    float* out = (float*)d_out;

    dim3 gridA(B_ * NK_ / RT, 2);
    proj_kernel<<<gridA, 128>>>(key, query, Wk, Wq);
    attn_kernel<<<PERSIST_BLOCKS, 256>>>(value, valid_lens, wv, out);
}

// round 9
// speedup vs baseline: 1.2575x; 1.2575x over previous
#include <cuda_runtime.h>

#define B_  16
#define NK_ 256
#define NQ_ 256
#define DK_ 256
#define H_  128
#define DV_ 256
#define KT  4     // k-rows per attn tile
#define RT  8     // rows per proj block

// scratch for projections (allocation-free rule: device globals)
__device__ float g_kproj[B_ * NK_ * H_];   // (B, NK, H)
__device__ float g_qproj[B_ * NQ_ * H_];   // (B, NQ, H)

__device__ __forceinline__ float tanh_fast(float x) {
    float y;
    asm("tanh.approx.f32 %0, %1;" : "=f"(y) : "f"(x));
    return y;
}

// ---------------------------------------------------------------------------
// Kernel A: projections, RT=8 rows per 128-thread block (R3/R7 config).
// blockIdx.y==0 -> key@Wk, 1 -> query@Wq.
// qproj rows with q >= valid_lens[b] are never read by attn -> early exit.
// ---------------------------------------------------------------------------
__global__ __launch_bounds__(128)
void proj_kernel(const float* __restrict__ key,
                 const float* __restrict__ query,
                 const float* __restrict__ Wk,
                 const float* __restrict__ Wq,
                 const int*   __restrict__ valid_lens) {
    const int r0 = blockIdx.x * RT;

    if (blockIdx.y) {
        // qproj block: rows are (b, q) with b = r0>>8, q = r0&255 .. +RT-1.
        // If the whole row-range is masked, skip all work.
        const int vl = valid_lens[r0 >> 8];
        if ((r0 & (NQ_ - 1)) >= vl) return;
    }

    __shared__ __align__(16) float rowsT[DK_ * RT];      // rowsT[d*RT + r]
    const float* in = blockIdx.y ? query : key;
    const float* W  = blockIdx.y ? Wq    : Wk;
    float* out      = blockIdx.y ? g_qproj : g_kproj;

    const int t = threadIdx.x;             // 0..127

    {
        const float* src = in + (size_t)r0 * DK_;
        int r = t >> 4;
        int d0 = (t & 15) * 16;
        #pragma unroll
        for (int i = 0; i < 4; ++i) {
            float4 v = *reinterpret_cast<const float4*>(src + r * DK_ + d0 + i * 4);
            rowsT[(d0 + i * 4 + 0) * RT + r] = v.x;
            rowsT[(d0 + i * 4 + 1) * RT + r] = v.y;
            rowsT[(d0 + i * 4 + 2) * RT + r] = v.z;
            rowsT[(d0 + i * 4 + 3) * RT + r] = v.w;
        }
    }
    __syncthreads();

    float acc[RT];
    #pragma unroll
    for (int r = 0; r < RT; ++r) acc[r] = 0.f;

    #pragma unroll 4
    for (int d = 0; d < DK_; ++d) {
        float w = W[d * H_ + t];
        float4 ra = *reinterpret_cast<const float4*>(&rowsT[d * RT]);
        float4 rb = *reinterpret_cast<const float4*>(&rowsT[d * RT + 4]);
        acc[0] = fmaf(ra.x, w, acc[0]);
        acc[1] = fmaf(ra.y, w, acc[1]);
        acc[2] = fmaf(ra.z, w, acc[2]);
        acc[3] = fmaf(ra.w, w, acc[3]);
        acc[4] = fmaf(rb.x, w, acc[4]);
        acc[5] = fmaf(rb.y, w, acc[5]);
        acc[6] = fmaf(rb.z, w, acc[6]);
        acc[7] = fmaf(rb.w, w, acc[7]);
    }

    #pragma unroll
    for (int r = 0; r < RT; ++r)
        out[(size_t)(r0 + r) * H_ + t] = acc[r];
}

// ---------------------------------------------------------------------------
// Kernel B: KT=4 k-rows per block, 256 threads, valid_lens early-skip.
// EXACT R7 champion body (static consecutive-block mapping, no-max softmax).
// ---------------------------------------------------------------------------
__global__ __launch_bounds__(256)
void attn_kernel(const float* __restrict__ value,
                 const int*   __restrict__ valid_lens,
                 const float* __restrict__ wv,
                 float*       __restrict__ out) {
    const int bk0 = blockIdx.x * KT;
    const int b   = bk0 >> 8;            // NK = 256
    const int t   = threadIdx.x;         // 0..255
    const int lane = t & 31;
    const int wid  = t >> 5;

    __shared__ __align__(16) float kvs[KT * H_];       // 2KB
    __shared__ __align__(16) float wvs[H_];
    __shared__ __align__(16) float attnT[NQ_ * KT];    // 4KB, attnT[q*KT + k]
    __shared__ float redm[KT][8];
    __shared__ float gred[KT];

    const int vl = valid_lens[b];

    // stage KT kproj rows + wv
    {
        const float* src = g_kproj + (size_t)bk0 * H_;   // 512 floats
        *reinterpret_cast<float2*>(&kvs[t * 2]) =
            *reinterpret_cast<const float2*>(src + t * 2);
        if (t < H_) wvs[t] = wv[t];
    }
    __syncthreads();

    // ---- Phase 1: scores + exp for q = t, all KT k (skip masked q) ----
    float e[KT];
    if (t < vl) {
        const float* qrow = g_qproj + (size_t)(b * NQ_ + t) * H_;
        float s[KT];
        #pragma unroll
        for (int k = 0; k < KT; ++k) s[k] = 0.f;

        #pragma unroll 2
        for (int h = 0; h < H_; h += 4) {
            float4 qv  = *reinterpret_cast<const float4*>(qrow + h);
            float4 wv4 = *reinterpret_cast<const float4*>(&wvs[h]);
            #pragma unroll
            for (int k = 0; k < KT; ++k) {
                float4 kv = *reinterpret_cast<const float4*>(&kvs[k * H_ + h]);
                s[k] = fmaf(wv4.x, tanh_fast(kv.x + qv.x), s[k]);
                s[k] = fmaf(wv4.y, tanh_fast(kv.y + qv.y), s[k]);
                s[k] = fmaf(wv4.z, tanh_fast(kv.z + qv.z), s[k]);
                s[k] = fmaf(wv4.w, tanh_fast(kv.w + qv.w), s[k]);
            }
        }
        #pragma unroll
        for (int k = 0; k < KT; ++k)
            e[k] = __expf(s[k]);          // |s| <= ~9, safe without max-sub
    } else {
        #pragma unroll
        for (int k = 0; k < KT; ++k) e[k] = 0.f;
    }

    // ---- Phase 2: sum-only softmax reduction per k over 256 q ----
    #pragma unroll
    for (int k = 0; k < KT; ++k) {
        float sm = e[k];
        #pragma unroll
        for (int o = 16; o > 0; o >>= 1)
            sm += __shfl_xor_sync(0xffffffffu, sm, o);
        if (lane == 0) redm[k][wid] = sm;
    }
    __syncthreads();
    if (t < 32) {                        // one warp: k = t>>3 (0..3)
        int k = t >> 3, w = t & 7;
        float v = redm[k][w];
        v += __shfl_xor_sync(0xffffffffu, v, 4);
        v += __shfl_xor_sync(0xffffffffu, v, 2);
        v += __shfl_xor_sync(0xffffffffu, v, 1);
        if (w == 0) gred[k] = v;
    }
    __syncthreads();

    {
        float4 a;
        a.x = e[0] * __frcp_rn(gred[0]);
        a.y = e[1] * __frcp_rn(gred[1]);
        a.z = e[2] * __frcp_rn(gred[2]);
        a.w = e[3] * __frcp_rn(gred[3]);
        *reinterpret_cast<float4*>(&attnT[t * KT]) = a;
    }
    __syncthreads();

    // ---- Phase 3: out[b, bk0+k, d], d = t; only q < vl contribute ----
    const float* vcol = value + (size_t)b * NQ_ * DV_ + t;
    float a0 = 0.f, a1 = 0.f, a2 = 0.f, a3 = 0.f;

    int q = 0;
    const int vl4 = vl & ~3;
    for (; q < vl4; q += 4) {
        #pragma unroll
        for (int j = 0; j < 4; ++j) {
            float v = vcol[(size_t)(q + j) * DV_];
            float4 a = *reinterpret_cast<const float4*>(&attnT[(q + j) * KT]);
            a0 = fmaf(a.x, v, a0);
            a1 = fmaf(a.y, v, a1);
            a2 = fmaf(a.z, v, a2);
            a3 = fmaf(a.w, v, a3);
        }
    }
    for (; q < vl; ++q) {
        float v = vcol[(size_t)q * DV_];
        float4 a = *reinterpret_cast<const float4*>(&attnT[q * KT]);
        a0 = fmaf(a.x, v, a0);
        a1 = fmaf(a.y, v, a1);
        a2 = fmaf(a.z, v, a2);
        a3 = fmaf(a.w, v, a3);
    }

    out[(size_t)(bk0 + 0) * DV_ + t] = a0;
    out[(size_t)(bk0 + 1) * DV_ + t] = a1;
    out[(size_t)(bk0 + 2) * DV_ + t] = a2;
    out[(size_t)(bk0 + 3) * DV_ + t] = a3;
}

// ---------------------------------------------------------------------------
extern "C" void kernel_launch(void* const* d_in, const int* in_sizes, int n_in,
                              void* d_out, int out_size) {
    const float* key        = (const float*)d_in[0];
    const float* query      = (const float*)d_in[1];
    const float* value      = (const float*)d_in[2];
    const int*   valid_lens = (const int*)  d_in[3];
    const float* Wk         = (const float*)d_in[4];
    const float* Wq         = (const float*)d_in[5];
    const float* wv         = (const float*)d_in[6];
    float* out = (float*)d_out;

    dim3 gridA(B_ * NK_ / RT, 2);
    proj_kernel<<<gridA, 128>>>(key, query, Wk, Wq, valid_lens);
    attn_kernel<<<B_ * NK_ / KT, 256>>>(value, valid_lens, wv, out);
}